// round 4
// baseline (speedup 1.0000x reference)
#include <cuda_runtime.h>
#include <cuda_bf16.h>

#define Bz 64
#define Tz 256
#define Ez 128
#define Hz 256
#define Zz 1024
#define Lz 9
#define WEz 100

#define LOG0  0
#define LENS0 147456
#define LL0   147520
#define TAGS0 147584

// ---------------- device scratch ----------------
__device__ __align__(16) float g_x[Bz*Tz*Ez];
__device__ __align__(16) float g_zx[2u*Tz*Bz*Zz];
__device__ __align__(16) float g_hs[Bz*Tz*2*Hz];
__device__ __align__(16) float g_hbuf[2][2][Bz*Hz];
__device__ unsigned int g_bar;

__device__ __forceinline__ float sigf(float x) { return 1.f / (1.f + __expf(-x)); }
__device__ __forceinline__ float tanhf_fast(float x) {
    float e = __expf(2.f * x);
    return 1.f - 2.f / (e + 1.f);
}

__global__ void init_kernel() { g_bar = 0u; }

// ---------------- 1) embed ----------------
__global__ void embed_kernel(const int* __restrict__ chars, const int* __restrict__ words,
                             const float* __restrict__ char_emb, const float* __restrict__ word_emb,
                             const float* __restrict__ W_word) {
    extern __shared__ float sm[];
    float* sW = sm;             // [100*128]
    float* srow = sm + WEz*Ez;  // [104]
    int tid = threadIdx.x;
    for (int i = tid; i < WEz*Ez; i += 128) sW[i] = W_word[i];
    int base = blockIdx.x * 128;
    for (int rr = 0; rr < 128; ++rr) {
        int bt = base + rr;
        __syncthreads();
        if (tid < WEz) srow[tid] = word_emb[(long)words[bt] * WEz + tid];
        __syncthreads();
        float acc = char_emb[(long)chars[bt] * Ez + tid];
        #pragma unroll 4
        for (int k = 0; k < WEz; ++k) acc = fmaf(srow[k], sW[k * Ez + tid], acc);
        g_x[bt * Ez + tid] = acc;
    }
}

// ---------------- 2) zx = x @ Wi + b (permuted store) ----------------
__global__ void gemm_zx_kernel(const float* __restrict__ Wi_f, const float* __restrict__ Wi_b,
                               const float* __restrict__ b_f, const float* __restrict__ b_b) {
    __shared__ float sA[16][68];
    __shared__ float sB[16][68];
    int tid = threadIdx.x;
    int bm = blockIdx.x, bn = blockIdx.y;
    int n0 = bn * 64;
    int dir = n0 >> 10;
    int n0l = n0 & 1023;
    const float* Wi   = dir ? Wi_b : Wi_f;
    const float* bias = dir ? b_b  : b_f;

    int tx = tid & 15, ty = tid >> 4;
    int lr = tid >> 2, lc = tid & 3;
    int br = tid >> 4, bc = tid & 15;

    float acc[4][4] = {};
    for (int kk = 0; kk < Ez; kk += 16) {
        float4 av = *(const float4*)&g_x[(bm*64 + lr)*Ez + kk + lc*4];
        float4 bv = *(const float4*)&Wi[(kk + br)*Zz + n0l + bc*4];
        __syncthreads();
        sA[lc*4+0][lr] = av.x; sA[lc*4+1][lr] = av.y;
        sA[lc*4+2][lr] = av.z; sA[lc*4+3][lr] = av.w;
        *(float4*)&sB[br][bc*4] = bv;
        __syncthreads();
        #pragma unroll
        for (int k = 0; k < 16; ++k) {
            float a[4], b[4];
            *(float4*)a = *(const float4*)&sA[k][ty*4];
            *(float4*)b = *(const float4*)&sB[k][tx*4];
            #pragma unroll
            for (int i = 0; i < 4; ++i)
                #pragma unroll
                for (int j = 0; j < 4; ++j)
                    acc[i][j] = fmaf(a[i], b[j], acc[i][j]);
        }
    }
    #pragma unroll
    for (int i = 0; i < 4; ++i) {
        int m = bm*64 + ty*4 + i;
        int b_ = m >> 8, t_ = m & 255;
        #pragma unroll
        for (int j = 0; j < 4; ++j) {
            int n1 = n0l + tx*4 + j;
            int gate = n1 >> 8, hc = n1 & 255;
            g_zx[(unsigned)dir*16777216u + ((unsigned)(t_*Bz + b_)*256u + hc)*4u + gate]
                = acc[i][j] + bias[n1];
        }
    }
}

// ---------------- 3) persistent bidirectional LSTM ----------------
#define LSTM_NBLK 128
__device__ __forceinline__ void grid_sync(int step) {
    __syncthreads();
    if (threadIdx.x == 0) {
        __threadfence();
        unsigned target = (unsigned)LSTM_NBLK * (unsigned)(step + 1);
        atomicAdd(&g_bar, 1u);
        unsigned v;
        do {
            asm volatile("ld.global.acquire.gpu.u32 %0, [%1];" : "=r"(v) : "l"(&g_bar));
        } while (v < target);
    }
    __syncthreads();
}

__global__ void __launch_bounds__(256, 1)
lstm_kernel(const float* __restrict__ Wh_f, const float* __restrict__ Wh_b) {
    extern __shared__ float sm[];
    float* sWh = sm;            // [16][260]
    float* sh  = sm + 16*260;   // [64][260]
    int tid = threadIdx.x;
    int dir = blockIdx.x >> 6;
    int cb  = blockIdx.x & 63;
    const float* Wh = dir ? Wh_b : Wh_f;

    int row = tid >> 2;
    int cg  = tid & 3;
    int hc  = cb*4 + cg;

    for (int i = tid; i < 16*256; i += 256) {
        int jj = i >> 8, k = i & 255;
        int gate = jj >> 2, c = jj & 3;
        sWh[jj*260 + k] = Wh[k*Zz + gate*256 + cb*4 + c];
    }

    const float4* sw4 = (const float4*)sWh;
    const float4* w0 = sw4 + (0*4 + cg)*65;
    const float4* w1 = sw4 + (1*4 + cg)*65;
    const float4* w2 = sw4 + (2*4 + cg)*65;
    const float4* w3 = sw4 + (3*4 + cg)*65;
    const float4* shr = (const float4*)sh + row*65;
    const float4* zx4 = (const float4*)g_zx + (unsigned)dir*4194304u;

    float c_state = 0.f;

    for (int step = 0; step < Tz; ++step) {
        int t = dir ? (Tz - 1 - step) : step;

        if (step > 0) {
            const float4* hsrc = (const float4*)&g_hbuf[dir][step & 1][0];
            #pragma unroll
            for (int it = 0; it < 16; ++it) {
                int i4 = it*256 + tid;
                float4 v = hsrc[i4];
                int hr = i4 >> 6, hq = i4 & 63;
                ((float4*)(sh + hr*260))[hq] = v;
            }
        }
        __syncthreads();

        float4 z0 = zx4[(unsigned)(t*Bz + row)*256u + hc];
        float a0 = z0.x, a1 = z0.y, a2 = z0.z, a3 = z0.w;

        if (step > 0) {
            #pragma unroll 4
            for (int q = 0; q < 64; ++q) {
                float4 h4 = shr[q];
                float4 wa = w0[q], wb = w1[q], wc = w2[q], wd = w3[q];
                a0 = fmaf(h4.x, wa.x, a0); a0 = fmaf(h4.y, wa.y, a0);
                a0 = fmaf(h4.z, wa.z, a0); a0 = fmaf(h4.w, wa.w, a0);
                a1 = fmaf(h4.x, wb.x, a1); a1 = fmaf(h4.y, wb.y, a1);
                a1 = fmaf(h4.z, wb.z, a1); a1 = fmaf(h4.w, wb.w, a1);
                a2 = fmaf(h4.x, wc.x, a2); a2 = fmaf(h4.y, wc.y, a2);
                a2 = fmaf(h4.z, wc.z, a2); a2 = fmaf(h4.w, wc.w, a2);
                a3 = fmaf(h4.x, wd.x, a3); a3 = fmaf(h4.y, wd.y, a3);
                a3 = fmaf(h4.z, wd.z, a3); a3 = fmaf(h4.w, wd.w, a3);
            }
        }

        float ig = sigf(a0), fg = sigf(a1), gg = tanhf_fast(a2), og = sigf(a3);
        c_state = fg * c_state + ig * gg;
        float h = og * tanhf_fast(c_state);

        g_hbuf[dir][(step + 1) & 1][row*Hz + hc] = h;
        g_hs[(unsigned)(row*Tz + t)*512u + dir*Hz + hc] = h;

        grid_sync(step);
    }
}

// ---------------- 4) logits = hs @ W_out + b_out ----------------
__global__ void logits_kernel(const float* __restrict__ W_out, const float* __restrict__ b_out,
                              float* __restrict__ out) {
    __shared__ float sW[512*Lz];
    __shared__ float sb[Lz];
    int tid = threadIdx.x;
    for (int i = tid; i < 512*Lz; i += 256) sW[i] = W_out[i];
    if (tid < Lz) sb[tid] = b_out[tid];
    __syncthreads();
    int row = blockIdx.x * 256 + tid;   // b*T + t
    const float4* hrow = (const float4*)(g_hs + (unsigned)row*512u);
    float acc[Lz] = {};
    for (int k4 = 0; k4 < 128; ++k4) {
        float4 h4 = hrow[k4];
        int k = k4*4;
        float hv[4] = {h4.x, h4.y, h4.z, h4.w};
        #pragma unroll
        for (int e = 0; e < 4; ++e)
            #pragma unroll
            for (int c = 0; c < Lz; ++c)
                acc[c] = fmaf(hv[e], sW[(k+e)*Lz + c], acc[c]);
    }
    #pragma unroll
    for (int c = 0; c < Lz; ++c)
        out[LOG0 + (unsigned)row*Lz + c] = acc[c] + sb[c];
}

// ---------------- 5) CRF: lens, score, log-norm, Viterbi ----------------
__global__ void crf_kernel(const int* __restrict__ chars, const int* __restrict__ labels,
                           const float* __restrict__ trans, float* __restrict__ out) {
    const float* logits = out + LOG0;
    int b = blockIdx.x;
    int lane = threadIdx.x;
    __shared__ unsigned char bps[255][16];

    float tr[Lz];
    if (lane < Lz) {
        #pragma unroll
        for (int i = 0; i < Lz; ++i) tr[i] = trans[i*Lz + lane];
    }

    // lens
    int cnt = 0;
    for (int t = lane; t < Tz; t += 32) cnt += (chars[b*Tz + t] != 0);
    #pragma unroll
    for (int off = 16; off; off >>= 1) cnt += __shfl_xor_sync(0xffffffffu, cnt, off);
    int len = cnt;

    // score
    float sc = 0.f;
    for (int t = lane; t < Tz; t += 32) {
        int lab = labels[b*Tz + t];
        if (t < len) {
            sc += logits[(unsigned)(b*Tz + t)*Lz + lab];
            if (t >= 1) sc += trans[labels[b*Tz + t - 1]*Lz + lab];
        }
    }
    #pragma unroll
    for (int off = 16; off; off >>= 1) sc += __shfl_xor_sync(0xffffffffu, sc, off);

    // forward (logsumexp) + viterbi (precise expf/logf — 255-step accumulation)
    float al = (lane < Lz) ? logits[(unsigned)(b*Tz)*Lz + lane] : -1e30f;
    float av = al;
    for (int t = 1; t < Tz; ++t) {
        float lg = (lane < Lz) ? logits[(unsigned)(b*Tz + t)*Lz + lane] : 0.f;
        float vals[Lz];
        float m1 = -1e30f, m2 = -1e30f;
        int arg = 0;
        #pragma unroll
        for (int i = 0; i < Lz; ++i) {
            float ai = __shfl_sync(0xffffffffu, al, i);
            float vi = __shfl_sync(0xffffffffu, av, i);
            float x1 = ai + tr[i];
            float x2 = vi + tr[i];
            vals[i] = x1;
            m1 = fmaxf(m1, x1);
            if (x2 > m2) { m2 = x2; arg = i; }
        }
        float s = 0.f;
        #pragma unroll
        for (int i = 0; i < Lz; ++i) s += expf(vals[i] - m1);
        float nal = m1 + logf(s) + lg;
        float nav = m2 + lg;
        bool active = (t < len);
        if (lane < Lz) {
            if (active) {
                al = nal; av = nav;
                bps[t-1][lane] = (unsigned char)arg;
            } else {
                bps[t-1][lane] = (unsigned char)lane;
            }
        }
    }
    __syncwarp();

    // final logsumexp over alpha — ALL lanes participate in the shuffles
    {
        float m = -1e30f;
        #pragma unroll
        for (int i = 0; i < Lz; ++i) m = fmaxf(m, __shfl_sync(0xffffffffu, al, i));
        float s = 0.f;
        #pragma unroll
        for (int i = 0; i < Lz; ++i) s += expf(__shfl_sync(0xffffffffu, al, i) - m);
        float lognorm = m + logf(s);
        if (lane == 0) {
            out[LL0 + b] = sc - lognorm;
            out[LENS0 + b] = (float)len;
        }
    }

    // Viterbi argmax over final alpha — all lanes participate
    float bestv = -1e30f; int bestidx = 0;
    #pragma unroll
    for (int i = 0; i < Lz; ++i) {
        float vi = __shfl_sync(0xffffffffu, av, i);
        if (vi > bestv) { bestv = vi; bestidx = i; }
    }
    if (lane == 0) {
        int tag = bestidx;
        out[TAGS0 + b*Tz + 255] = (float)tag;
        for (int k = 254; k >= 0; --k) {
            tag = bps[k][tag];
            out[TAGS0 + b*Tz + k] = (float)tag;
        }
    }
}

// ---------------- launch ----------------
extern "C" void kernel_launch(void* const* d_in, const int* in_sizes, int n_in,
                              void* d_out, int out_size) {
    const int*   chars    = (const int*)d_in[0];
    const int*   words    = (const int*)d_in[1];
    const int*   labels   = (const int*)d_in[2];
    const float* char_emb = (const float*)d_in[3];
    const float* word_emb = (const float*)d_in[4];
    const float* W_word   = (const float*)d_in[5];
    const float* Wi_f     = (const float*)d_in[6];
    const float* Wh_f     = (const float*)d_in[7];
    const float* b_f      = (const float*)d_in[8];
    const float* Wi_b     = (const float*)d_in[9];
    const float* Wh_b     = (const float*)d_in[10];
    const float* b_b      = (const float*)d_in[11];
    const float* W_out    = (const float*)d_in[12];
    const float* b_out    = (const float*)d_in[13];
    const float* trans    = (const float*)d_in[14];
    float* out = (float*)d_out;

    cudaFuncSetAttribute(embed_kernel, cudaFuncAttributeMaxDynamicSharedMemorySize, 51616);
    cudaFuncSetAttribute(lstm_kernel,  cudaFuncAttributeMaxDynamicSharedMemorySize, 83200);

    init_kernel<<<1, 1>>>();
    embed_kernel<<<128, 128, 51616>>>(chars, words, char_emb, word_emb, W_word);
    gemm_zx_kernel<<<dim3(256, 32), 256>>>(Wi_f, Wi_b, b_f, b_b);
    lstm_kernel<<<LSTM_NBLK, 256, 83200>>>(Wh_f, Wh_b);
    logits_kernel<<<64, 256>>>(W_out, b_out, out);
    crf_kernel<<<Bz, 32>>>(chars, labels, trans, out);
}

// round 5
// speedup vs baseline: 1.2779x; 1.2779x over previous
#include <cuda_runtime.h>
#include <cuda_bf16.h>

#define Bz 64
#define Tz 256
#define Ez 128
#define Hz 256
#define Zz 1024
#define Lz 9
#define WEz 100

#define LOG0  0
#define LENS0 147456
#define LL0   147520
#define TAGS0 147584

// ---------------- device scratch ----------------
__device__ __align__(16) float g_x[Bz*Tz*Ez];
__device__ __align__(16) float g_zx[2u*Tz*Bz*Zz];
__device__ __align__(16) float g_hs[Bz*Tz*2*Hz];
__device__ __align__(16) float g_hbuf[2][2][Hz*Bz];   // transposed: [dir][parity][hc*64+row]
__device__ unsigned int g_bar;

__device__ __forceinline__ float sigf(float x) { return 1.f / (1.f + __expf(-x)); }
__device__ __forceinline__ float tanhf_fast(float x) {
    float e = __expf(2.f * x);
    return 1.f - 2.f / (e + 1.f);
}

__global__ void init_kernel() { g_bar = 0u; }

// ---------------- 1) embed ----------------
__global__ void embed_kernel(const int* __restrict__ chars, const int* __restrict__ words,
                             const float* __restrict__ char_emb, const float* __restrict__ word_emb,
                             const float* __restrict__ W_word) {
    extern __shared__ float sm[];
    float* sW = sm;             // [100*128]
    float* srow = sm + WEz*Ez;  // [104]
    int tid = threadIdx.x;
    for (int i = tid; i < WEz*Ez; i += 128) sW[i] = W_word[i];
    int base = blockIdx.x * 128;
    for (int rr = 0; rr < 128; ++rr) {
        int bt = base + rr;
        __syncthreads();
        if (tid < WEz) srow[tid] = word_emb[(long)words[bt] * WEz + tid];
        __syncthreads();
        float acc = char_emb[(long)chars[bt] * Ez + tid];
        #pragma unroll 4
        for (int k = 0; k < WEz; ++k) acc = fmaf(srow[k], sW[k * Ez + tid], acc);
        g_x[bt * Ez + tid] = acc;
    }
}

// ---------------- 2) zx = x @ Wi + b (permuted store) ----------------
__global__ void gemm_zx_kernel(const float* __restrict__ Wi_f, const float* __restrict__ Wi_b,
                               const float* __restrict__ b_f, const float* __restrict__ b_b) {
    __shared__ float sA[16][68];
    __shared__ float sB[16][68];
    int tid = threadIdx.x;
    int bm = blockIdx.x, bn = blockIdx.y;
    int n0 = bn * 64;
    int dir = n0 >> 10;
    int n0l = n0 & 1023;
    const float* Wi   = dir ? Wi_b : Wi_f;
    const float* bias = dir ? b_b  : b_f;

    int tx = tid & 15, ty = tid >> 4;
    int lr = tid >> 2, lc = tid & 3;
    int br = tid >> 4, bc = tid & 15;

    float acc[4][4] = {};
    for (int kk = 0; kk < Ez; kk += 16) {
        float4 av = *(const float4*)&g_x[(bm*64 + lr)*Ez + kk + lc*4];
        float4 bv = *(const float4*)&Wi[(kk + br)*Zz + n0l + bc*4];
        __syncthreads();
        sA[lc*4+0][lr] = av.x; sA[lc*4+1][lr] = av.y;
        sA[lc*4+2][lr] = av.z; sA[lc*4+3][lr] = av.w;
        *(float4*)&sB[br][bc*4] = bv;
        __syncthreads();
        #pragma unroll
        for (int k = 0; k < 16; ++k) {
            float a[4], b[4];
            *(float4*)a = *(const float4*)&sA[k][ty*4];
            *(float4*)b = *(const float4*)&sB[k][tx*4];
            #pragma unroll
            for (int i = 0; i < 4; ++i)
                #pragma unroll
                for (int j = 0; j < 4; ++j)
                    acc[i][j] = fmaf(a[i], b[j], acc[i][j]);
        }
    }
    #pragma unroll
    for (int i = 0; i < 4; ++i) {
        int m = bm*64 + ty*4 + i;
        int b_ = m >> 8, t_ = m & 255;
        #pragma unroll
        for (int j = 0; j < 4; ++j) {
            int n1 = n0l + tx*4 + j;
            int gate = n1 >> 8, hc = n1 & 255;
            g_zx[(unsigned)dir*16777216u + ((unsigned)(t_*Bz + b_)*256u + hc)*4u + gate]
                = acc[i][j] + bias[n1];
        }
    }
}

// ---------------- 3) persistent bidirectional LSTM (register-tiled, k-split) ----------------
#define LSTM_NBLK 128
__device__ __forceinline__ void grid_sync(int step) {
    __syncthreads();
    if (threadIdx.x == 0) {
        __threadfence();
        unsigned target = (unsigned)LSTM_NBLK * (unsigned)(step + 1);
        atomicAdd(&g_bar, 1u);
        unsigned v;
        do {
            asm volatile("ld.global.acquire.gpu.u32 %0, [%1];" : "=r"(v) : "l"(&g_bar));
        } while (v < target);
    }
    __syncthreads();
}

// Block: dir (blockIdx>>6), cb (blockIdx&63) -> hc columns cb*4..cb*4+3.
// Thread tid = rg*16 + hcg*4 + kg:
//   rg  in 0..15: rows rg*4 .. rg*4+3
//   hcg in 0..3 : hc = cb*4+hcg (4 gates)
//   kg  in 0..3 : k-slice, k = q*4+kg
// smem: sh[k][row] stride 68, sw[k][zcol(jj=hcg*4+g)] stride 24.
__global__ void __launch_bounds__(256, 1)
lstm_kernel(const float* __restrict__ Wh_f, const float* __restrict__ Wh_b) {
    extern __shared__ float sm[];
    float* sh = sm;             // [256][68]  h transposed (17408 floats)
    float* sw = sm + 256*68;    // [256][24]  weights (6144 floats)
    int tid = threadIdx.x;
    int dir = blockIdx.x >> 6;
    int cb  = blockIdx.x & 63;
    const float* Wh = dir ? Wh_b : Wh_f;

    int kg  = tid & 3;
    int hcg = (tid >> 2) & 3;
    int rg  = tid >> 4;
    int hc  = cb*4 + hcg;
    int myrow = rg*4 + kg;

    // fill sw once: sw[k*24 + hcg2*4 + g] = Wh[k][g*256 + cb*4 + hcg2]
    for (int i = tid; i < 4096; i += 256) {
        int k = i >> 4, j = i & 15;
        int g = j & 3, hcg2 = j >> 2;
        sw[k*24 + j] = Wh[k*Zz + g*256 + cb*4 + hcg2];
    }

    const float* zx = g_zx + (unsigned)dir*16777216u;
    const float* ph_base = sh + (unsigned)kg*68u + (unsigned)rg*4u;
    const float* pw_base = sw + (unsigned)kg*24u + (unsigned)hcg*4u;

    float c_state = 0.f;

    for (int step = 0; step < Tz; ++step) {
        int t = dir ? (Tz - 1 - step) : step;

        if (step > 0) {
            // transpose-copy g_hbuf_T[hc][row] -> sh[k=hc][row] (float4, conflict-free)
            const float4* src = (const float4*)&g_hbuf[dir][step & 1][0];
            #pragma unroll
            for (int it = 0; it < 16; ++it) {
                int i4 = it*256 + tid;
                float4 v = src[i4];
                int hcI = i4 >> 4, r4 = i4 & 15;
                *(float4*)&sh[hcI*68 + r4*4] = v;
            }
        }
        __syncthreads();

        float a[4][4] = {{0.f,0.f,0.f,0.f},{0.f,0.f,0.f,0.f},
                         {0.f,0.f,0.f,0.f},{0.f,0.f,0.f,0.f}};

        if (step > 0) {
            const float* ph = ph_base;
            const float* pw = pw_base;
            #pragma unroll 4
            for (int q = 0; q < 64; ++q) {
                float4 h4 = *(const float4*)ph;
                float4 w4 = *(const float4*)pw;
                ph += 4*68;
                pw += 4*24;
                a[0][0] = fmaf(h4.x, w4.x, a[0][0]);
                a[0][1] = fmaf(h4.x, w4.y, a[0][1]);
                a[0][2] = fmaf(h4.x, w4.z, a[0][2]);
                a[0][3] = fmaf(h4.x, w4.w, a[0][3]);
                a[1][0] = fmaf(h4.y, w4.x, a[1][0]);
                a[1][1] = fmaf(h4.y, w4.y, a[1][1]);
                a[1][2] = fmaf(h4.y, w4.z, a[1][2]);
                a[1][3] = fmaf(h4.y, w4.w, a[1][3]);
                a[2][0] = fmaf(h4.z, w4.x, a[2][0]);
                a[2][1] = fmaf(h4.z, w4.y, a[2][1]);
                a[2][2] = fmaf(h4.z, w4.z, a[2][2]);
                a[2][3] = fmaf(h4.z, w4.w, a[2][3]);
                a[3][0] = fmaf(h4.w, w4.x, a[3][0]);
                a[3][1] = fmaf(h4.w, w4.y, a[3][1]);
                a[3][2] = fmaf(h4.w, w4.z, a[3][2]);
                a[3][3] = fmaf(h4.w, w4.w, a[3][3]);
            }
        }

        // reduce partials across the 4 kg lanes (butterfly)
        #pragma unroll
        for (int i = 0; i < 4; ++i) {
            #pragma unroll
            for (int g = 0; g < 4; ++g) {
                float v = a[i][g];
                v += __shfl_xor_sync(0xffffffffu, v, 1);
                v += __shfl_xor_sync(0xffffffffu, v, 2);
                a[i][g] = v;
            }
        }

        // this lane owns row = rg*4+kg
        float4 z0 = *(const float4*)&zx[((unsigned)(t*Bz + myrow)*256u + hc)*4u];
        float zi = z0.x + a[kg][0];
        float zf = z0.y + a[kg][1];
        float zg = z0.z + a[kg][2];
        float zo = z0.w + a[kg][3];

        float ig = sigf(zi), fg = sigf(zf), gg = tanhf_fast(zg), og = sigf(zo);
        c_state = fg * c_state + ig * gg;
        float h = og * tanhf_fast(c_state);

        g_hbuf[dir][(step + 1) & 1][hc*Bz + myrow] = h;   // 4 kg lanes -> 16B coalesced
        g_hs[(unsigned)(myrow*Tz + t)*512u + dir*Hz + hc] = h;

        grid_sync(step);
    }
}

// ---------------- 4) logits = hs @ W_out + b_out ----------------
__global__ void logits_kernel(const float* __restrict__ W_out, const float* __restrict__ b_out,
                              float* __restrict__ out) {
    __shared__ float sW[512*Lz];
    __shared__ float sb[Lz];
    int tid = threadIdx.x;
    for (int i = tid; i < 512*Lz; i += 256) sW[i] = W_out[i];
    if (tid < Lz) sb[tid] = b_out[tid];
    __syncthreads();
    int row = blockIdx.x * 256 + tid;   // b*T + t
    const float4* hrow = (const float4*)(g_hs + (unsigned)row*512u);
    float acc[Lz] = {};
    for (int k4 = 0; k4 < 128; ++k4) {
        float4 h4 = hrow[k4];
        int k = k4*4;
        float hv[4] = {h4.x, h4.y, h4.z, h4.w};
        #pragma unroll
        for (int e = 0; e < 4; ++e)
            #pragma unroll
            for (int c = 0; c < Lz; ++c)
                acc[c] = fmaf(hv[e], sW[(k+e)*Lz + c], acc[c]);
    }
    #pragma unroll
    for (int c = 0; c < Lz; ++c)
        out[LOG0 + (unsigned)row*Lz + c] = acc[c] + sb[c];
}

// ---------------- 5) CRF: lens, score, log-norm, Viterbi ----------------
__global__ void crf_kernel(const int* __restrict__ chars, const int* __restrict__ labels,
                           const float* __restrict__ trans, float* __restrict__ out) {
    const float* logits = out + LOG0;
    int b = blockIdx.x;
    int lane = threadIdx.x;
    __shared__ unsigned char bps[255][16];

    float tr[Lz];
    if (lane < Lz) {
        #pragma unroll
        for (int i = 0; i < Lz; ++i) tr[i] = trans[i*Lz + lane];
    }

    // lens
    int cnt = 0;
    for (int t = lane; t < Tz; t += 32) cnt += (chars[b*Tz + t] != 0);
    #pragma unroll
    for (int off = 16; off; off >>= 1) cnt += __shfl_xor_sync(0xffffffffu, cnt, off);
    int len = cnt;

    // score
    float sc = 0.f;
    for (int t = lane; t < Tz; t += 32) {
        int lab = labels[b*Tz + t];
        if (t < len) {
            sc += logits[(unsigned)(b*Tz + t)*Lz + lab];
            if (t >= 1) sc += trans[labels[b*Tz + t - 1]*Lz + lab];
        }
    }
    #pragma unroll
    for (int off = 16; off; off >>= 1) sc += __shfl_xor_sync(0xffffffffu, sc, off);

    // forward (logsumexp) + viterbi
    float al = (lane < Lz) ? logits[(unsigned)(b*Tz)*Lz + lane] : -1e30f;
    float av = al;
    for (int t = 1; t < Tz; ++t) {
        float lg = (lane < Lz) ? logits[(unsigned)(b*Tz + t)*Lz + lane] : 0.f;
        float vals[Lz];
        float m1 = -1e30f, m2 = -1e30f;
        int arg = 0;
        #pragma unroll
        for (int i = 0; i < Lz; ++i) {
            float ai = __shfl_sync(0xffffffffu, al, i);
            float vi = __shfl_sync(0xffffffffu, av, i);
            float x1 = ai + tr[i];
            float x2 = vi + tr[i];
            vals[i] = x1;
            m1 = fmaxf(m1, x1);
            if (x2 > m2) { m2 = x2; arg = i; }
        }
        float s = 0.f;
        #pragma unroll
        for (int i = 0; i < Lz; ++i) s += expf(vals[i] - m1);
        float nal = m1 + logf(s) + lg;
        float nav = m2 + lg;
        bool active = (t < len);
        if (lane < Lz) {
            if (active) {
                al = nal; av = nav;
                bps[t-1][lane] = (unsigned char)arg;
            } else {
                bps[t-1][lane] = (unsigned char)lane;
            }
        }
    }
    __syncwarp();

    // final logsumexp over alpha — all lanes participate
    {
        float m = -1e30f;
        #pragma unroll
        for (int i = 0; i < Lz; ++i) m = fmaxf(m, __shfl_sync(0xffffffffu, al, i));
        float s = 0.f;
        #pragma unroll
        for (int i = 0; i < Lz; ++i) s += expf(__shfl_sync(0xffffffffu, al, i) - m);
        float lognorm = m + logf(s);
        if (lane == 0) {
            out[LL0 + b] = sc - lognorm;
            out[LENS0 + b] = (float)len;
        }
    }

    // Viterbi argmax over final alpha — all lanes participate
    float bestv = -1e30f; int bestidx = 0;
    #pragma unroll
    for (int i = 0; i < Lz; ++i) {
        float vi = __shfl_sync(0xffffffffu, av, i);
        if (vi > bestv) { bestv = vi; bestidx = i; }
    }
    if (lane == 0) {
        int tag = bestidx;
        out[TAGS0 + b*Tz + 255] = (float)tag;
        for (int k = 254; k >= 0; --k) {
            tag = bps[k][tag];
            out[TAGS0 + b*Tz + k] = (float)tag;
        }
    }
}

// ---------------- launch ----------------
extern "C" void kernel_launch(void* const* d_in, const int* in_sizes, int n_in,
                              void* d_out, int out_size) {
    const int*   chars    = (const int*)d_in[0];
    const int*   words    = (const int*)d_in[1];
    const int*   labels   = (const int*)d_in[2];
    const float* char_emb = (const float*)d_in[3];
    const float* word_emb = (const float*)d_in[4];
    const float* W_word   = (const float*)d_in[5];
    const float* Wi_f     = (const float*)d_in[6];
    const float* Wh_f     = (const float*)d_in[7];
    const float* b_f      = (const float*)d_in[8];
    const float* Wi_b     = (const float*)d_in[9];
    const float* Wh_b     = (const float*)d_in[10];
    const float* b_b      = (const float*)d_in[11];
    const float* W_out    = (const float*)d_in[12];
    const float* b_out    = (const float*)d_in[13];
    const float* trans    = (const float*)d_in[14];
    float* out = (float*)d_out;

    cudaFuncSetAttribute(embed_kernel, cudaFuncAttributeMaxDynamicSharedMemorySize, 51616);
    cudaFuncSetAttribute(lstm_kernel,  cudaFuncAttributeMaxDynamicSharedMemorySize, 96000);

    init_kernel<<<1, 1>>>();
    embed_kernel<<<128, 128, 51616>>>(chars, words, char_emb, word_emb, W_word);
    gemm_zx_kernel<<<dim3(256, 32), 256>>>(Wi_f, Wi_b, b_f, b_b);
    lstm_kernel<<<LSTM_NBLK, 256, 94208>>>(Wh_f, Wh_b);
    logits_kernel<<<64, 256>>>(W_out, b_out, out);
    crf_kernel<<<Bz, 32>>>(chars, labels, trans, out);
}